// round 16
// baseline (speedup 1.0000x reference)
#include <cuda_runtime.h>
#include <cuda_fp16.h>
#include <math.h>
#include <stdint.h>

#define TSZ 2048
#define HN  16
#define DH  64
#define CL  64
#define NCHUNK 32
#define TS  72                  // fp32 staging stride (floats)
#define SH  72                  // half tile stride (halves)

#define GM 8192
#define GN 1024
#define GK 1024

// Scratch
__device__ __half g_projh[3][(size_t)64 * TSZ * DH];  // q,k,v fp16: 48 MB
__device__ float  g_projf[2][(size_t)64 * TSZ * DH];  // aK,aC fp32: 64 MB
__device__ __half g_o2dh[(size_t)GM * GN];            // 16 MB
__device__ __half g_xh[(size_t)GM * GK];              // 16 MB
__device__ __half g_wth[6][(size_t)GN * GK];          // 12 MB  W^T [z][n][k]

__device__ __forceinline__ void ldsm_x4(unsigned& r0, unsigned& r1,
                                        unsigned& r2, unsigned& r3,
                                        uint32_t addr) {
    asm volatile("ldmatrix.sync.aligned.m8n8.x4.shared.b16 {%0,%1,%2,%3}, [%4];"
                 : "=r"(r0), "=r"(r1), "=r"(r2), "=r"(r3) : "r"(addr));
}
__device__ __forceinline__ void ldsm_x2(unsigned& r0, unsigned& r1,
                                        uint32_t addr) {
    asm volatile("ldmatrix.sync.aligned.m8n8.x2.shared.b16 {%0,%1}, [%2];"
                 : "=r"(r0), "=r"(r1) : "r"(addr));
}

// ---------------------------------------------------------------------------
// Prep: fp16(x) and fp16(W^T).
// ---------------------------------------------------------------------------
__global__ __launch_bounds__(256) void half_x_kernel(
    const float* __restrict__ x, __half* __restrict__ xh)
{
    size_t i = ((size_t)blockIdx.x * 256 + threadIdx.x) * 8;
    float4 v0 = *(const float4*)(x + i);
    float4 v1 = *(const float4*)(x + i + 4);
    __half2 h[4];
    h[0] = __floats2half2_rn(v0.x, v0.y);
    h[1] = __floats2half2_rn(v0.z, v0.w);
    h[2] = __floats2half2_rn(v1.x, v1.y);
    h[3] = __floats2half2_rn(v1.z, v1.w);
    *(uint4*)(xh + i) = *(uint4*)h;
}

__global__ __launch_bounds__(256) void half_wt_kernel(
    const float* __restrict__ Wq, const float* __restrict__ Wk,
    const float* __restrict__ Wv, const float* __restrict__ WgK,
    const float* __restrict__ WgC, const float* __restrict__ Wo,
    __half* __restrict__ wth)
{
    __shared__ float tile[32][33];
    const int z = blockIdx.z;
    const float* W = (z == 0) ? Wq : (z == 1) ? Wk : (z == 2) ? Wv
                   : (z == 3) ? WgK : (z == 4) ? WgC : Wo;
    const int n0 = blockIdx.x * 32, k0 = blockIdx.y * 32;
    const int tx = threadIdx.x & 31, ty = threadIdx.x >> 5;
#pragma unroll
    for (int i = 0; i < 4; i++)
        tile[ty + i * 8][tx] = W[(size_t)(k0 + ty + i * 8) * GN + n0 + tx];
    __syncthreads();
    __half* dst = wth + (size_t)z * GN * GK;
#pragma unroll
    for (int i = 0; i < 4; i++)
        dst[(size_t)(n0 + ty + i * 8) * GK + k0 + tx] =
            __float2half_rn(tile[tx][ty + i * 8]);
}

// ---------------------------------------------------------------------------
// FP16 mma GEMM, 512 threads (16 warps = 2m x 8n, warp tile 64x32).
// 3-stage cp.async pipeline (wait_group 1).
// mode: 0 plain fp32 row-major; 1 permuted fp16 (q/k/v); 2 permuted fp32
// sigmoid (gates).
// ---------------------------------------------------------------------------
#define AST2 72
#define BST2 72
#define STG_A_EL (128 * AST2)                 // 9216 halves
#define STG_EL   (STG_A_EL + 256 * BST2)      // 27648 halves per stage
#define GEMM2_SMEM (3 * STG_EL * (int)sizeof(__half))   // 165888 B

__device__ __forceinline__ void gemm2_fill(const __half* __restrict__ A,
                                           const __half* __restrict__ BT,
                                           int rowBase, int colBase, int tid,
                                           __half* stage, int kt)
{
    const int k0 = kt * 64;
    __half* AsD = stage;
    __half* BsD = stage + STG_A_EL;
#pragma unroll
    for (int i = 0; i < 2; i++) {
        const int id = tid + i * 512;
        const int r = id >> 3, c = (id & 7) * 8;
        const __half* src = A + (size_t)(rowBase + r) * GK + k0 + c;
        unsigned dst = (unsigned)__cvta_generic_to_shared(AsD + r * AST2 + c);
        asm volatile("cp.async.cg.shared.global [%0], [%1], 16;" :: "r"(dst), "l"(src));
    }
#pragma unroll
    for (int i = 0; i < 4; i++) {
        const int id = tid + i * 512;
        const int r = id >> 3, c = (id & 7) * 8;
        const __half* src = BT + (size_t)(colBase + r) * GK + k0 + c;
        unsigned dst = (unsigned)__cvta_generic_to_shared(BsD + r * BST2 + c);
        asm volatile("cp.async.cg.shared.global [%0], [%1], 16;" :: "r"(dst), "l"(src));
    }
    asm volatile("cp.async.commit_group;");
}

__global__ __launch_bounds__(512, 1) void gemm_fp16(
    const __half* __restrict__ A, const __half* __restrict__ WTall,
    const float* __restrict__ b3, const float* __restrict__ b4,
    float* __restrict__ Cf, __half* __restrict__ Chb, int multi)
{
    extern __shared__ __half smem[];

    const int tid  = threadIdx.x;
    const int lane = tid & 31;
    const int warpId = tid >> 5;
    const int wm = warpId & 1;
    const int wn = warpId >> 1;
    const int g  = lane >> 2;
    const int tg = lane & 3;
    const int rowBase = blockIdx.y * 128;
    const int colBase = blockIdx.x * 256;

    const uint32_t laneAoff =
        (uint32_t)((((lane & 15) * AST2) + ((lane >> 4) << 3)) * 2);
    const int brow = (lane & 7) + ((lane >> 4) << 3);
    const int bko  = ((lane >> 3) & 1) << 3;
    const uint32_t laneBoff = (uint32_t)((brow * BST2 + bko) * 2);

    const size_t PS = (size_t)64 * TSZ * DH;
    const __half* BT; const float* bias; float* C; __half* Ch; int mode;
    if (multi) {
        const int z = blockIdx.z;
        BT = WTall + (size_t)z * GN * GK;
        if (z < 3) {
            Ch = Chb + (size_t)z * PS; C = nullptr; bias = nullptr; mode = 1;
        } else {
            C = Cf + (size_t)(z - 3) * PS; Ch = nullptr;
            bias = (z == 3) ? b3 : b4; mode = 2;
        }
    } else {
        BT = WTall; bias = nullptr; C = Cf; Ch = nullptr; mode = 0;
    }

    float acc[4][4][4];
#pragma unroll
    for (int i = 0; i < 4; i++)
#pragma unroll
        for (int j = 0; j < 4; j++)
#pragma unroll
            for (int e = 0; e < 4; e++) acc[i][j][e] = 0.f;

    const int KT = GK / 64;
    gemm2_fill(A, BT, rowBase, colBase, tid, smem, 0);
    gemm2_fill(A, BT, rowBase, colBase, tid, smem + STG_EL, 1);

    int buf = 0;
    for (int kt = 0; kt < KT; kt++) {
        if (kt < KT - 1) asm volatile("cp.async.wait_group 1;");
        else             asm volatile("cp.async.wait_group 0;");
        __syncthreads();
        if (kt + 2 < KT) {
            const int nb3 = (buf + 2 >= 3) ? buf - 1 : buf + 2;
            gemm2_fill(A, BT, rowBase, colBase, tid, smem + nb3 * STG_EL, kt + 2);
        }

        const __half* As = smem + buf * STG_EL;
        const __half* Bs = As + STG_A_EL;
        const uint32_t asb = (uint32_t)__cvta_generic_to_shared(As)
                           + (uint32_t)(wm * 64 * AST2 * 2) + laneAoff;
        const uint32_t bsb = (uint32_t)__cvta_generic_to_shared(Bs)
                           + (uint32_t)(wn * 32 * BST2 * 2) + laneBoff;

#pragma unroll
        for (int kk = 0; kk < 4; kk++) {
            const uint32_t kb2 = kk * 32;   // bytes
            unsigned af[4][4], bf[4][2];
#pragma unroll
            for (int mi = 0; mi < 4; mi++)
                ldsm_x4(af[mi][0], af[mi][1], af[mi][2], af[mi][3],
                        asb + mi * 16 * AST2 * 2 + kb2);
#pragma unroll
            for (int j = 0; j < 2; j++)
                ldsm_x4(bf[2 * j][0], bf[2 * j][1],
                        bf[2 * j + 1][0], bf[2 * j + 1][1],
                        bsb + j * 16 * BST2 * 2 + kb2);
#pragma unroll
            for (int ni = 0; ni < 4; ni++)
#pragma unroll
                for (int mi = 0; mi < 4; mi++) {
                    asm volatile(
                        "mma.sync.aligned.m16n8k16.row.col.f32.f16.f16.f32 "
                        "{%0,%1,%2,%3}, {%4,%5,%6,%7}, {%8,%9}, {%0,%1,%2,%3};\n"
                        : "+f"(acc[mi][ni][0]), "+f"(acc[mi][ni][1]),
                          "+f"(acc[mi][ni][2]), "+f"(acc[mi][ni][3])
                        : "r"(af[mi][0]), "r"(af[mi][1]),
                          "r"(af[mi][2]), "r"(af[mi][3]),
                          "r"(bf[ni][0]), "r"(bf[ni][1]));
                }
        }
        buf = (buf + 1 >= 3) ? 0 : buf + 1;
    }

#pragma unroll
    for (int mi = 0; mi < 4; mi++) {
        const int gr0 = rowBase + wm * 64 + mi * 16 + g;
#pragma unroll
        for (int ni = 0; ni < 4; ni++) {
            const int gc = colBase + wn * 32 + ni * 8 + 2 * tg;
#pragma unroll
            for (int half = 0; half < 2; half++) {
                const int gr = gr0 + 8 * half;
                float v0 = acc[mi][ni][2 * half];
                float v1 = acc[mi][ni][2 * half + 1];
                if (mode == 0) {
                    *(float2*)&C[(size_t)gr * GN + gc] = make_float2(v0, v1);
                } else {
                    const int b = gr >> 11, t = gr & 2047;
                    const int h = gc >> 6,  d = gc & 63;
                    const size_t idx =
                        ((size_t)((b * HN + h) * TSZ + t)) * DH + d;
                    if (mode == 1) {
                        *(__half2*)&Ch[idx] = __floats2half2_rn(v0, v1);
                    } else {
                        v0 = 1.f / (1.f + __expf(-(v0 + bias[gc])));
                        v1 = 1.f / (1.f + __expf(-(v1 + bias[gc + 1])));
                        *(float2*)&C[idx] = make_float2(v0, v1);
                    }
                }
            }
        }
    }
}

// ---------------------------------------------------------------------------
// Chunked scan, dv-split, fp16 mma + ldmatrix, 512 threads, warp-group task
// parallelism; phase F runs concurrently with phase E (fp32-only state
// updates; fp16 state conversion deferred to next chunk's derive phase).
// ---------------------------------------------------------------------------
#define O_QS   0
#define O_KS   9216
#define O_AKF  36864
#define O_ACF  55296
#define O_SF   73728
#define O_CTF  92160
#define O_GTF  101376
#define HB     110592
#define O_QH   (HB + 0)
#define O_KH   (HB + 9216)
#define O_QT   (HB + 18432)
#define O_QTT  (HB + 27648)
#define O_KT   (HB + 36864)
#define O_KTT  (HB + 46080)
#define O_PH   (HB + 55296)
#define O_RS   (HB + 64512)
#define O_UH   (HB + 73728)
#define O_SHH  (HB + 82944)
#define O_VT   (HB + 92160)
#define O_KCT  (HB + 96768)
#define O_CTH  (HB + 101376)
#define O_GTH  (HB + 105984)
#define SCAN_SMEM_BYTES (HB + 110592)

template<int NI>
__device__ __forceinline__ void zacc(float (&acc)[NI][4]) {
#pragma unroll
    for (int i = 0; i < NI; i++)
#pragma unroll
        for (int j = 0; j < 4; j++) acc[i][j] = 0.f;
}

template<int NI, bool NEGA>
__device__ __forceinline__ void mmh(const __half* __restrict__ A,
                                    const __half* __restrict__ B,
                                    float (&acc)[NI][4],
                                    int lane, int mb, int nb)
{
    const uint32_t abase = (uint32_t)__cvta_generic_to_shared(
        A + (mb + (lane & 15)) * SH + ((lane >> 4) << 3));
    const int brow = (lane & 7) + ((lane >> 4) << 3);
    const int bko  = ((lane >> 3) & 1) << 3;
    const uint32_t bbase = (uint32_t)__cvta_generic_to_shared(
        B + (nb + brow) * SH + bko);
#pragma unroll
    for (int kk = 0; kk < 4; kk++) {
        const uint32_t kb2 = kk * 32;
        unsigned a0, a1, a2, a3;
        ldsm_x4(a0, a1, a2, a3, abase + kb2);
        if (NEGA) {
            a0 ^= 0x80008000u; a1 ^= 0x80008000u;
            a2 ^= 0x80008000u; a3 ^= 0x80008000u;
        }
#pragma unroll
        for (int j = 0; j < NI / 2; j++) {
            unsigned b0, b1, b2, b3;
            ldsm_x4(b0, b1, b2, b3, bbase + (uint32_t)(j * 16 * SH * 2) + kb2);
            asm volatile(
                "mma.sync.aligned.m16n8k16.row.col.f32.f16.f16.f32 "
                "{%0,%1,%2,%3}, {%4,%5,%6,%7}, {%8,%9}, {%0,%1,%2,%3};\n"
                : "+f"(acc[2 * j][0]), "+f"(acc[2 * j][1]),
                  "+f"(acc[2 * j][2]), "+f"(acc[2 * j][3])
                : "r"(a0), "r"(a1), "r"(a2), "r"(a3), "r"(b0), "r"(b1));
            asm volatile(
                "mma.sync.aligned.m16n8k16.row.col.f32.f16.f16.f32 "
                "{%0,%1,%2,%3}, {%4,%5,%6,%7}, {%8,%9}, {%0,%1,%2,%3};\n"
                : "+f"(acc[2 * j + 1][0]), "+f"(acc[2 * j + 1][1]),
                  "+f"(acc[2 * j + 1][2]), "+f"(acc[2 * j + 1][3])
                : "r"(a0), "r"(a1), "r"(a2), "r"(a3), "r"(b2), "r"(b3));
        }
    }
}

template<int NI, int MASK, bool SCALE>
__device__ __forceinline__ void storeH(__half* __restrict__ O,
    const float* __restrict__ scl, float (&acc)[NI][4],
    int g, int tg, int mb, int nb)
{
#pragma unroll
    for (int ni = 0; ni < NI; ni++) {
        const int c0 = nb + ni * 8 + 2 * tg;
#pragma unroll
        for (int hh = 0; hh < 2; hh++) {
            const int r = mb + g + 8 * hh;
            float v0 = acc[ni][2 * hh];
            float v1 = acc[ni][2 * hh + 1];
            if (MASK == 1) { if (c0 > r) v0 = 0.f; if (c0 + 1 > r) v1 = 0.f; }
            if (MASK == 2) { if (c0 >= r) v0 = 0.f; if (c0 + 1 >= r) v1 = 0.f; }
            if (SCALE) { v0 *= scl[r * TS + c0]; v1 *= scl[r * TS + c0 + 1]; }
            *(__half2*)&O[r * SH + c0] = __floats2half2_rn(v0, v1);
        }
    }
}

template<int NI>
__device__ __forceinline__ void storeHT(__half* __restrict__ O,
    float (&acc)[NI][4], int g, int tg, int mb, int nb)
{
#pragma unroll
    for (int ni = 0; ni < NI; ni++) {
        const int c0 = nb + ni * 8 + 2 * tg;
#pragma unroll
        for (int hh = 0; hh < 2; hh++) {
            const int r = mb + g + 8 * hh;
#pragma unroll
            for (int e = 0; e < 2; e++)
                O[(c0 + e) * SH + r] = __float2half_rn(acc[ni][2 * hh + e]);
        }
    }
}

template<int NI>
__device__ __forceinline__ void updateS(float* __restrict__ Sf,
    __half* __restrict__ Sh, const float* __restrict__ rs,
    float (&acc)[NI][4], int g, int tg, int mb, int nb)
{
#pragma unroll
    for (int ni = 0; ni < NI; ni++) {
        const int c0 = nb + ni * 8 + 2 * tg;
#pragma unroll
        for (int hh = 0; hh < 2; hh++) {
            const int r = mb + g + 8 * hh;
            const float rr = rs[r];
            float v0 = rr * rs[c0]     * (Sf[r * TS + c0]     + acc[ni][2 * hh]);
            float v1 = rr * rs[c0 + 1] * (Sf[r * TS + c0 + 1] + acc[ni][2 * hh + 1]);
            *(float2*)&Sf[r * TS + c0] = make_float2(v0, v1);
            *(__half2*)&Sh[r * SH + c0] = __floats2half2_rn(v0, v1);
        }
    }
}

// fp32-only transposed-state update (half conversion deferred to derive).
template<int NI>
__device__ __forceinline__ void updateTF(float* __restrict__ Tf,
    const float* __restrict__ rs,
    float (&acc)[NI][4], int g, int tg, int mb, int nb)
{
#pragma unroll
    for (int ni = 0; ni < NI; ni++) {
        const int c0 = nb + ni * 8 + 2 * tg;
#pragma unroll
        for (int hh = 0; hh < 2; hh++) {
            const int r = mb + g + 8 * hh;
            float v0 = rs[c0]     * (Tf[r * TS + c0]     + acc[ni][2 * hh]);
            float v1 = rs[c0 + 1] * (Tf[r * TS + c0 + 1] + acc[ni][2 * hh + 1]);
            *(float2*)&Tf[r * TS + c0] = make_float2(v0, v1);
        }
    }
}

// cp.async prefetch: q,k fp16 tiles + aK,aC fp32 tiles = 3072 chunks.
__device__ __forceinline__ void scan_prefetch(
    const __half* __restrict__ q, const __half* __restrict__ k,
    const float* __restrict__ aK, const float* __restrict__ aC,
    uint32_t smbase, int tid, size_t off)
{
#pragma unroll
    for (int i = 0; i < 6; i++) {
        const int id = tid + i * 512;
        uint32_t dst;
        const void* src;
        if (id < 1024) {
            const int t8 = id >> 9, loc = id & 511;
            const int r = loc >> 3, c8 = (loc & 7) * 8;
            const __half* s = (t8 == 0) ? q : k;
            src = s + off + (size_t)loc * 8;
            dst = smbase + (uint32_t)(t8 * 9216 + (r * SH + c8) * 2);
        } else {
            const int t4 = (id - 1024) >> 10, loc = (id - 1024) & 1023;
            const int r = loc >> 4, c4 = (loc & 15) * 4;
            const float* s = (t4 == 0) ? aK : aC;
            src = s + off + (size_t)loc * 4;
            dst = smbase + (uint32_t)(O_AKF + t4 * 18432 + (r * TS + c4) * 4);
        }
        asm volatile("cp.async.cg.shared.global [%0], [%1], 16;" :: "r"(dst), "l"(src));
    }
    asm volatile("cp.async.commit_group;");
}

__global__ __launch_bounds__(512) void scan_chunked(
    const __half* __restrict__ qp, const __half* __restrict__ kp,
    const __half* __restrict__ vp, const float* __restrict__ aKp,
    const float* __restrict__ aCp, __half* __restrict__ o2dh)
{
    extern __shared__ char smc[];
    __half* QS  = (__half*)(smc + O_QS);
    __half* KS  = (__half*)(smc + O_KS);
    float*  AKf = (float*)(smc + O_AKF);
    float*  ACf = (float*)(smc + O_ACF);
    float*  Sf  = (float*)(smc + O_SF);
    float*  CTf = (float*)(smc + O_CTF);
    float*  GTf = (float*)(smc + O_GTF);
    __half* Qh  = (__half*)(smc + O_QH);
    __half* Kh  = (__half*)(smc + O_KH);
    __half* Qt  = (__half*)(smc + O_QT);
    __half* QtT = (__half*)(smc + O_QTT);
    __half* Kt  = (__half*)(smc + O_KT);
    __half* KtT = (__half*)(smc + O_KTT);
    __half* Ph  = (__half*)(smc + O_PH);
    __half* RSc = (__half*)(smc + O_RS);
    __half* Uh  = (__half*)(smc + O_UH);
    __half* Sh  = (__half*)(smc + O_SHH);
    __half* VT  = (__half*)(smc + O_VT);
    __half* KCT = (__half*)(smc + O_KCT);
    __half* CTh = (__half*)(smc + O_CTH);
    __half* GTh = (__half*)(smc + O_GTH);
    __shared__ float aKL[64], aCL[64];

    const int bh   = blockIdx.x >> 1;
    const int half = blockIdx.x & 1;
    const int b = bh >> 4, h = bh & 15;
    const size_t base = (size_t)bh * TSZ * DH;
    const int tid  = threadIdx.x;
    const int lane = tid & 31, w = tid >> 5;
    const int wg = w >> 3, w8 = w & 7;
    const int g = lane >> 2, tg = lane & 3;
    const int mb4 = (w8 & 3) * 16, nb4 = (w8 >> 2) * 32;
    const int mb2 = (w8 & 3) * 16, nb2 = (w8 >> 2) * 16;
    const int mbF = (w8 & 1) * 16, nbF = (w8 >> 1) * 16;
    const uint32_t smbase = (uint32_t)__cvta_generic_to_shared(smc);

    for (int i = tid; i < 9216; i += 512) ((uint32_t*)(smc + O_SF))[i] = 0;
    for (int i = tid; i < 2304; i += 512) ((uint32_t*)(smc + O_SHH))[i] = 0;
    for (int i = tid; i < 2304; i += 512) ((uint32_t*)(smc + O_CTH))[i] = 0;

    scan_prefetch(qp, kp, aKp, aCp, smbase, tid, base);
    __syncthreads();

    for (int ch = 0; ch < NCHUNK; ch++) {
        const size_t off = base + (size_t)ch * CL * DH;
        {   // V (fp16 source) half-column -> VT transposed
            const int r = tid >> 3, c4 = (tid & 7) * 4;
            __half2 hv[2];
            *(uint2*)hv = *(const uint2*)(vp + off + r * DH + half * 32 + c4);
            VT[(c4 + 0) * SH + r] = __low2half(hv[0]);
            VT[(c4 + 1) * SH + r] = __high2half(hv[0]);
            VT[(c4 + 2) * SH + r] = __low2half(hv[1]);
            VT[(c4 + 3) * SH + r] = __high2half(hv[1]);
        }
        asm volatile("cp.async.wait_group 0;");
        __syncthreads();

        {   // cumulative products: 2 tensors x 4 segments of 16 rows
            float* Tt = (tid < 256) ? AKf : ACf;
            const int col = tid & 63;
            const int seg = (tid >> 6) & 3;
            const int r0 = seg * 16;
            float p = 1.f;
#pragma unroll
            for (int r = 0; r < 16; r++) {
                p *= Tt[(r0 + r) * TS + col];
                Tt[(r0 + r) * TS + col] = p;
            }
            __syncthreads();
            float pref = 1.f;
#pragma unroll
            for (int s = 0; s < 3; s++)
                if (s < seg) pref *= Tt[(s * 16 + 15) * TS + col];
            __syncthreads();
            if (seg > 0) {
#pragma unroll
                for (int r = 0; r < 16; r++) Tt[(r0 + r) * TS + col] *= pref;
            }
        }
        __syncthreads();

        // derive fp16 operand tiles (+ SCL fp32) + deferred state conversion
#pragma unroll
        for (int i = 0; i < 8; i++) {
            const int e = tid + i * 512;
            const int r = e >> 6, c = e & 63;
            const int idx = r * TS + c;
            const float ak = AKf[idx], ac = ACf[idx];
            const float qv = __half2float(QS[r * SH + c]);
            const float kv = __half2float(KS[r * SH + c]);
            if (r == 63) { aKL[c] = ak; aCL[c] = ac; }
            const float qh = qv * ak, kt = kv / ak;
            const float qt = qv / ac, kh = kv * ac;
            Qh[r * SH + c]  = __float2half_rn(qh);
            Kh[r * SH + c]  = __float2half_rn(kh);
            Qt[r * SH + c]  = __float2half_rn(qt);
            QtT[c * SH + r] = __float2half_rn(qt);
            Kt[r * SH + c]  = __float2half_rn(kt);
            KtT[c * SH + r] = __float2half_rn(kt);
            AKf[idx] = ak * ac;          // SCL
        }
        // convert fp32 C/G states (from previous chunk's F) to fp16
#pragma unroll
        for (int i = 0; i < 4; i++) {
            const int e = tid + i * 512;          // 0..2047 = 32x64
            const int r = e >> 6, c = e & 63;
            CTh[r * SH + c] = __float2half_rn(CTf[r * TS + c]);
            GTh[r * SH + c] = __float2half_rn(GTf[r * TS + c]);
        }
        __syncthreads();

        float acc4[4][4];
        float acc2[2][4];

        // Phase A
        if (wg == 0) {
            zacc(acc4);
            mmh<4, false>(Kh, Qt, acc4, lane, mb4, nb4);
            storeH<4, 2, false>(RSc, nullptr, acc4, g, tg, mb4, nb4);
        } else {
            zacc(acc4);
            mmh<4, false>(Qh, Kt, acc4, lane, mb4, nb4);
            storeH<4, 1, false>(Ph, nullptr, acc4, g, tg, mb4, nb4);
        }
        __syncthreads();

        // Phase B
        if (wg == 0) {
            zacc(acc2);
            mmh<2, false>(Kh,  CTh, acc2, lane, mb2, nb2);
            mmh<2, false>(RSc, VT,  acc2, lane, mb2, nb2);
            storeHT<2>(KCT, acc2, g, tg, mb2, nb2);
        } else {
            zacc(acc4);
            mmh<4, false>(Qh, Sh,  acc4, lane, mb4, nb4);
            mmh<4, false>(Ph, KtT, acc4, lane, mb4, nb4);
            storeH<4, 0, true>(Uh, AKf, acc4, g, tg, mb4, nb4);
        }
        __syncthreads();

        // staging dead: prefetch next chunk
        {
            int chn = ch + 1; if (chn > NCHUNK - 1) chn = NCHUNK - 1;
            scan_prefetch(qp, kp, aKp, aCp, smbase, tid,
                          base + (size_t)chn * CL * DH);
        }

        // Phase C
        if (wg == 0) {
            zacc(acc4);
            mmh<4, false>(Uh, Qt, acc4, lane, mb4, nb4);
            storeH<4, 1, false>(RSc, nullptr, acc4, g, tg, mb4, nb4);
        } else {
            zacc(acc4);
            mmh<4, false>(KtT, KtT, acc4, lane, mb4, nb4);
            updateS<4>(Sf, Sh, aKL, acc4, g, tg, mb4, nb4);
        }
        __syncthreads();

        // Phase E (wg0: output) || Phase F (wg1: fp32 C/G state updates)
        if (wg == 0) {
            zacc(acc2);
            mmh<2, false>(Uh,  CTh, acc2, lane, mb2, nb2);
            mmh<2, false>(RSc, VT,  acc2, lane, mb2, nb2);
            mmh<2, true >(Qh,  GTh, acc2, lane, mb2, nb2);
            mmh<2, true >(Ph,  KCT, acc2, lane, mb2, nb2);
            const int t0 = ch * CL;
#pragma unroll
            for (int ni = 0; ni < 2; ni++) {
                const int c0 = nb2 + ni * 8 + 2 * tg;
#pragma unroll
                for (int hh = 0; hh < 2; hh++) {
                    const int r = mb2 + g + 8 * hh;
                    __half2 st = __floats2half2_rn(acc2[ni][2 * hh],
                                                   acc2[ni][2 * hh + 1]);
                    *(__half2*)&o2dh[(size_t)(b * TSZ + t0 + r) * 1024 +
                                     h * DH + half * 32 + c0] = st;
                }
            }
        } else {
            zacc(acc2);
            mmh<2, false>(VT, QtT, acc2, lane, mbF, nbF);
            updateTF<2>(CTf, aCL, acc2, g, tg, mbF, nbF);
            zacc(acc2);
            mmh<2, false>(KCT, KtT, acc2, lane, mbF, nbF);
            updateTF<2>(GTf, aKL, acc2, g, tg, mbF, nbF);
        }
        __syncthreads();
    }
}

// ---------------------------------------------------------------------------
extern "C" void kernel_launch(void* const* d_in, const int* in_sizes, int n_in,
                              void* d_out, int out_size)
{
    const float* x   = (const float*)d_in[0];
    const float* Wq  = (const float*)d_in[1];
    const float* Wk  = (const float*)d_in[2];
    const float* Wv  = (const float*)d_in[3];
    const float* WgK = (const float*)d_in[4];
    const float* bgK = (const float*)d_in[5];
    const float* WgC = (const float*)d_in[6];
    const float* bgC = (const float*)d_in[7];
    const float* Wo  = (const float*)d_in[8];
    float* out = (float*)d_out;

    __half *projh = nullptr, *o2dh = nullptr, *xh = nullptr, *wth = nullptr;
    float  *projf = nullptr;
    cudaGetSymbolAddress((void**)&projh, g_projh);
    cudaGetSymbolAddress((void**)&projf, g_projf);
    cudaGetSymbolAddress((void**)&o2dh,  g_o2dh);
    cudaGetSymbolAddress((void**)&xh,    g_xh);
    cudaGetSymbolAddress((void**)&wth,   g_wth);
    const size_t PS = (size_t)64 * TSZ * DH;

    cudaFuncSetAttribute(gemm_fp16,
                         cudaFuncAttributeMaxDynamicSharedMemorySize,
                         GEMM2_SMEM);
    cudaFuncSetAttribute(scan_chunked,
                         cudaFuncAttributeMaxDynamicSharedMemorySize,
                         SCAN_SMEM_BYTES);

    half_x_kernel<<<(GM * GK) / 2048, 256>>>(x, xh);
    half_wt_kernel<<<dim3(32, 32, 6), 256>>>(Wq, Wk, Wv, WgK, WgC, Wo, wth);

    gemm_fp16<<<dim3(GN / 256, GM / 128, 5), 512, GEMM2_SMEM>>>(
        xh, wth, bgK, bgC, projf, projh, 1);

    scan_chunked<<<128, 512, SCAN_SMEM_BYTES>>>(
        projh, projh + PS, projh + 2 * PS, projf, projf + PS, o2dh);

    gemm_fp16<<<dim3(GN / 256, GM / 128, 1), 512, GEMM2_SMEM>>>(
        o2dh, wth + (size_t)5 * GN * GK, nullptr, nullptr, out, nullptr, 0);
}

// round 17
// speedup vs baseline: 1.0366x; 1.0366x over previous
#include <cuda_runtime.h>
#include <cuda_fp16.h>
#include <math.h>
#include <stdint.h>

#define TSZ 2048
#define HN  16
#define DH  64
#define CL  64
#define NCHUNK 32
#define TS  72                  // fp32 staging stride (floats)
#define SH  72                  // half tile stride (halves)

#define GM 8192
#define GN 1024
#define GK 1024

// Scratch
__device__ __half g_projh[3][(size_t)64 * TSZ * DH];  // q,k,v fp16: 48 MB
__device__ float  g_projf[2][(size_t)64 * TSZ * DH];  // aK,aC fp32: 64 MB
__device__ __half g_o2dh[(size_t)GM * GN];            // 16 MB
__device__ __half g_xh[(size_t)GM * GK];              // 16 MB
__device__ __half g_wth[6][(size_t)GN * GK];          // 12 MB  W^T [z][n][k]

__device__ __forceinline__ void ldsm_x4(unsigned& r0, unsigned& r1,
                                        unsigned& r2, unsigned& r3,
                                        uint32_t addr) {
    asm volatile("ldmatrix.sync.aligned.m8n8.x4.shared.b16 {%0,%1,%2,%3}, [%4];"
                 : "=r"(r0), "=r"(r1), "=r"(r2), "=r"(r3) : "r"(addr));
}

// ---------------------------------------------------------------------------
// Prep: fp16(x) and fp16(W^T).
// ---------------------------------------------------------------------------
__global__ __launch_bounds__(256) void half_x_kernel(
    const float* __restrict__ x, __half* __restrict__ xh)
{
    size_t i = ((size_t)blockIdx.x * 256 + threadIdx.x) * 8;
    float4 v0 = *(const float4*)(x + i);
    float4 v1 = *(const float4*)(x + i + 4);
    __half2 h[4];
    h[0] = __floats2half2_rn(v0.x, v0.y);
    h[1] = __floats2half2_rn(v0.z, v0.w);
    h[2] = __floats2half2_rn(v1.x, v1.y);
    h[3] = __floats2half2_rn(v1.z, v1.w);
    *(uint4*)(xh + i) = *(uint4*)h;
}

__global__ __launch_bounds__(256) void half_wt_kernel(
    const float* __restrict__ Wq, const float* __restrict__ Wk,
    const float* __restrict__ Wv, const float* __restrict__ WgK,
    const float* __restrict__ WgC, const float* __restrict__ Wo,
    __half* __restrict__ wth)
{
    __shared__ float tile[32][33];
    const int z = blockIdx.z;
    const float* W = (z == 0) ? Wq : (z == 1) ? Wk : (z == 2) ? Wv
                   : (z == 3) ? WgK : (z == 4) ? WgC : Wo;
    const int n0 = blockIdx.x * 32, k0 = blockIdx.y * 32;
    const int tx = threadIdx.x & 31, ty = threadIdx.x >> 5;
#pragma unroll
    for (int i = 0; i < 4; i++)
        tile[ty + i * 8][tx] = W[(size_t)(k0 + ty + i * 8) * GN + n0 + tx];
    __syncthreads();
    __half* dst = wth + (size_t)z * GN * GK;
#pragma unroll
    for (int i = 0; i < 4; i++)
        dst[(size_t)(n0 + ty + i * 8) * GK + k0 + tx] =
            __float2half_rn(tile[tx][ty + i * 8]);
}

// ---------------------------------------------------------------------------
// FP16 mma GEMM, 512 threads (16 warps = 2m x 8n, warp tile 64x32).
// Two-stage cp.async pipeline (round-15 version; static kt&1 buffering).
// mode: 0 plain fp32 row-major; 1 permuted fp16 (q/k/v); 2 permuted fp32
// sigmoid (gates).
// ---------------------------------------------------------------------------
#define AST2 72
#define BST2 72
#define AS2_EL (128 * AST2)
#define BS2_EL (256 * BST2)
#define GEMM2_SMEM ((2 * (AS2_EL + BS2_EL)) * (int)sizeof(__half))

__device__ __forceinline__ void gemm2_fill(const __half* __restrict__ A,
                                           const __half* __restrict__ BT,
                                           int rowBase, int colBase, int tid,
                                           __half* AsD, __half* BsD, int kt)
{
    const int k0 = kt * 64;
#pragma unroll
    for (int i = 0; i < 2; i++) {
        const int id = tid + i * 512;
        const int r = id >> 3, c = (id & 7) * 8;
        const __half* src = A + (size_t)(rowBase + r) * GK + k0 + c;
        unsigned dst = (unsigned)__cvta_generic_to_shared(AsD + r * AST2 + c);
        asm volatile("cp.async.cg.shared.global [%0], [%1], 16;" :: "r"(dst), "l"(src));
    }
#pragma unroll
    for (int i = 0; i < 4; i++) {
        const int id = tid + i * 512;
        const int r = id >> 3, c = (id & 7) * 8;
        const __half* src = BT + (size_t)(colBase + r) * GK + k0 + c;
        unsigned dst = (unsigned)__cvta_generic_to_shared(BsD + r * BST2 + c);
        asm volatile("cp.async.cg.shared.global [%0], [%1], 16;" :: "r"(dst), "l"(src));
    }
    asm volatile("cp.async.commit_group;");
}

__global__ __launch_bounds__(512, 1) void gemm_fp16(
    const __half* __restrict__ A, const __half* __restrict__ WTall,
    const float* __restrict__ b3, const float* __restrict__ b4,
    float* __restrict__ Cf, __half* __restrict__ Chb, int multi)
{
    extern __shared__ __half smem[];
    __half* AsB = smem;
    __half* BsB = smem + 2 * AS2_EL;

    const int tid  = threadIdx.x;
    const int lane = tid & 31;
    const int warpId = tid >> 5;
    const int wm = warpId & 1;
    const int wn = warpId >> 1;
    const int g  = lane >> 2;
    const int tg = lane & 3;
    const int rowBase = blockIdx.y * 128;
    const int colBase = blockIdx.x * 256;

    const uint32_t laneAoff =
        (uint32_t)((((lane & 15) * AST2) + ((lane >> 4) << 3)) * 2);
    const int brow = (lane & 7) + ((lane >> 4) << 3);
    const int bko  = ((lane >> 3) & 1) << 3;
    const uint32_t laneBoff = (uint32_t)((brow * BST2 + bko) * 2);

    const size_t PS = (size_t)64 * TSZ * DH;
    const __half* BT; const float* bias; float* C; __half* Ch; int mode;
    if (multi) {
        const int z = blockIdx.z;
        BT = WTall + (size_t)z * GN * GK;
        if (z < 3) {
            Ch = Chb + (size_t)z * PS; C = nullptr; bias = nullptr; mode = 1;
        } else {
            C = Cf + (size_t)(z - 3) * PS; Ch = nullptr;
            bias = (z == 3) ? b3 : b4; mode = 2;
        }
    } else {
        BT = WTall; bias = nullptr; C = Cf; Ch = nullptr; mode = 0;
    }

    float acc[4][4][4];
#pragma unroll
    for (int i = 0; i < 4; i++)
#pragma unroll
        for (int j = 0; j < 4; j++)
#pragma unroll
            for (int e = 0; e < 4; e++) acc[i][j][e] = 0.f;

    gemm2_fill(A, BT, rowBase, colBase, tid, AsB, BsB, 0);

    const int KT = GK / 64;
    for (int kt = 0; kt < KT; kt++) {
        const int cur = kt & 1;
        asm volatile("cp.async.wait_group 0;");
        __syncthreads();
        if (kt + 1 < KT)
            gemm2_fill(A, BT, rowBase, colBase, tid,
                       AsB + (cur ^ 1) * AS2_EL, BsB + (cur ^ 1) * BS2_EL, kt + 1);

        const __half* As = AsB + cur * AS2_EL;
        const __half* Bs = BsB + cur * BS2_EL;
        const uint32_t asb = (uint32_t)__cvta_generic_to_shared(As)
                           + (uint32_t)(wm * 64 * AST2 * 2) + laneAoff;
        const uint32_t bsb = (uint32_t)__cvta_generic_to_shared(Bs)
                           + (uint32_t)(wn * 32 * BST2 * 2) + laneBoff;

#pragma unroll
        for (int kk = 0; kk < 4; kk++) {
            const uint32_t kb2 = kk * 32;   // bytes
            unsigned af[4][4], bf[4][2];
#pragma unroll
            for (int mi = 0; mi < 4; mi++)
                ldsm_x4(af[mi][0], af[mi][1], af[mi][2], af[mi][3],
                        asb + mi * 16 * AST2 * 2 + kb2);
#pragma unroll
            for (int j = 0; j < 2; j++)
                ldsm_x4(bf[2 * j][0], bf[2 * j][1],
                        bf[2 * j + 1][0], bf[2 * j + 1][1],
                        bsb + j * 16 * BST2 * 2 + kb2);
#pragma unroll
            for (int ni = 0; ni < 4; ni++)
#pragma unroll
                for (int mi = 0; mi < 4; mi++) {
                    asm volatile(
                        "mma.sync.aligned.m16n8k16.row.col.f32.f16.f16.f32 "
                        "{%0,%1,%2,%3}, {%4,%5,%6,%7}, {%8,%9}, {%0,%1,%2,%3};\n"
                        : "+f"(acc[mi][ni][0]), "+f"(acc[mi][ni][1]),
                          "+f"(acc[mi][ni][2]), "+f"(acc[mi][ni][3])
                        : "r"(af[mi][0]), "r"(af[mi][1]),
                          "r"(af[mi][2]), "r"(af[mi][3]),
                          "r"(bf[ni][0]), "r"(bf[ni][1]));
                }
        }
    }

#pragma unroll
    for (int mi = 0; mi < 4; mi++) {
        const int gr0 = rowBase + wm * 64 + mi * 16 + g;
#pragma unroll
        for (int ni = 0; ni < 4; ni++) {
            const int gc = colBase + wn * 32 + ni * 8 + 2 * tg;
#pragma unroll
            for (int half = 0; half < 2; half++) {
                const int gr = gr0 + 8 * half;
                float v0 = acc[mi][ni][2 * half];
                float v1 = acc[mi][ni][2 * half + 1];
                if (mode == 0) {
                    *(float2*)&C[(size_t)gr * GN + gc] = make_float2(v0, v1);
                } else {
                    const int b = gr >> 11, t = gr & 2047;
                    const int h = gc >> 6,  d = gc & 63;
                    const size_t idx =
                        ((size_t)((b * HN + h) * TSZ + t)) * DH + d;
                    if (mode == 1) {
                        *(__half2*)&Ch[idx] = __floats2half2_rn(v0, v1);
                    } else {
                        v0 = 1.f / (1.f + __expf(-(v0 + bias[gc])));
                        v1 = 1.f / (1.f + __expf(-(v1 + bias[gc + 1])));
                        *(float2*)&C[idx] = make_float2(v0, v1);
                    }
                }
            }
        }
    }
}

// ---------------------------------------------------------------------------
// Chunked scan (round-16 version, unchanged): dv-split, fp16 mma + ldmatrix,
// 512 threads, warp-group task parallelism; phase F concurrent with phase E.
// ---------------------------------------------------------------------------
#define O_QS   0
#define O_KS   9216
#define O_AKF  36864
#define O_ACF  55296
#define O_SF   73728
#define O_CTF  92160
#define O_GTF  101376
#define HB     110592
#define O_QH   (HB + 0)
#define O_KH   (HB + 9216)
#define O_QT   (HB + 18432)
#define O_QTT  (HB + 27648)
#define O_KT   (HB + 36864)
#define O_KTT  (HB + 46080)
#define O_PH   (HB + 55296)
#define O_RS   (HB + 64512)
#define O_UH   (HB + 73728)
#define O_SHH  (HB + 82944)
#define O_VT   (HB + 92160)
#define O_KCT  (HB + 96768)
#define O_CTH  (HB + 101376)
#define O_GTH  (HB + 105984)
#define SCAN_SMEM_BYTES (HB + 110592)

template<int NI>
__device__ __forceinline__ void zacc(float (&acc)[NI][4]) {
#pragma unroll
    for (int i = 0; i < NI; i++)
#pragma unroll
        for (int j = 0; j < 4; j++) acc[i][j] = 0.f;
}

template<int NI, bool NEGA>
__device__ __forceinline__ void mmh(const __half* __restrict__ A,
                                    const __half* __restrict__ B,
                                    float (&acc)[NI][4],
                                    int lane, int mb, int nb)
{
    const uint32_t abase = (uint32_t)__cvta_generic_to_shared(
        A + (mb + (lane & 15)) * SH + ((lane >> 4) << 3));
    const int brow = (lane & 7) + ((lane >> 4) << 3);
    const int bko  = ((lane >> 3) & 1) << 3;
    const uint32_t bbase = (uint32_t)__cvta_generic_to_shared(
        B + (nb + brow) * SH + bko);
#pragma unroll
    for (int kk = 0; kk < 4; kk++) {
        const uint32_t kb2 = kk * 32;
        unsigned a0, a1, a2, a3;
        ldsm_x4(a0, a1, a2, a3, abase + kb2);
        if (NEGA) {
            a0 ^= 0x80008000u; a1 ^= 0x80008000u;
            a2 ^= 0x80008000u; a3 ^= 0x80008000u;
        }
#pragma unroll
        for (int j = 0; j < NI / 2; j++) {
            unsigned b0, b1, b2, b3;
            ldsm_x4(b0, b1, b2, b3, bbase + (uint32_t)(j * 16 * SH * 2) + kb2);
            asm volatile(
                "mma.sync.aligned.m16n8k16.row.col.f32.f16.f16.f32 "
                "{%0,%1,%2,%3}, {%4,%5,%6,%7}, {%8,%9}, {%0,%1,%2,%3};\n"
                : "+f"(acc[2 * j][0]), "+f"(acc[2 * j][1]),
                  "+f"(acc[2 * j][2]), "+f"(acc[2 * j][3])
                : "r"(a0), "r"(a1), "r"(a2), "r"(a3), "r"(b0), "r"(b1));
            asm volatile(
                "mma.sync.aligned.m16n8k16.row.col.f32.f16.f16.f32 "
                "{%0,%1,%2,%3}, {%4,%5,%6,%7}, {%8,%9}, {%0,%1,%2,%3};\n"
                : "+f"(acc[2 * j + 1][0]), "+f"(acc[2 * j + 1][1]),
                  "+f"(acc[2 * j + 1][2]), "+f"(acc[2 * j + 1][3])
                : "r"(a0), "r"(a1), "r"(a2), "r"(a3), "r"(b2), "r"(b3));
        }
    }
}

template<int NI, int MASK, bool SCALE>
__device__ __forceinline__ void storeH(__half* __restrict__ O,
    const float* __restrict__ scl, float (&acc)[NI][4],
    int g, int tg, int mb, int nb)
{
#pragma unroll
    for (int ni = 0; ni < NI; ni++) {
        const int c0 = nb + ni * 8 + 2 * tg;
#pragma unroll
        for (int hh = 0; hh < 2; hh++) {
            const int r = mb + g + 8 * hh;
            float v0 = acc[ni][2 * hh];
            float v1 = acc[ni][2 * hh + 1];
            if (MASK == 1) { if (c0 > r) v0 = 0.f; if (c0 + 1 > r) v1 = 0.f; }
            if (MASK == 2) { if (c0 >= r) v0 = 0.f; if (c0 + 1 >= r) v1 = 0.f; }
            if (SCALE) { v0 *= scl[r * TS + c0]; v1 *= scl[r * TS + c0 + 1]; }
            *(__half2*)&O[r * SH + c0] = __floats2half2_rn(v0, v1);
        }
    }
}

template<int NI>
__device__ __forceinline__ void storeHT(__half* __restrict__ O,
    float (&acc)[NI][4], int g, int tg, int mb, int nb)
{
#pragma unroll
    for (int ni = 0; ni < NI; ni++) {
        const int c0 = nb + ni * 8 + 2 * tg;
#pragma unroll
        for (int hh = 0; hh < 2; hh++) {
            const int r = mb + g + 8 * hh;
#pragma unroll
            for (int e = 0; e < 2; e++)
                O[(c0 + e) * SH + r] = __float2half_rn(acc[ni][2 * hh + e]);
        }
    }
}

template<int NI>
__device__ __forceinline__ void updateS(float* __restrict__ Sf,
    __half* __restrict__ Sh, const float* __restrict__ rs,
    float (&acc)[NI][4], int g, int tg, int mb, int nb)
{
#pragma unroll
    for (int ni = 0; ni < NI; ni++) {
        const int c0 = nb + ni * 8 + 2 * tg;
#pragma unroll
        for (int hh = 0; hh < 2; hh++) {
            const int r = mb + g + 8 * hh;
            const float rr = rs[r];
            float v0 = rr * rs[c0]     * (Sf[r * TS + c0]     + acc[ni][2 * hh]);
            float v1 = rr * rs[c0 + 1] * (Sf[r * TS + c0 + 1] + acc[ni][2 * hh + 1]);
            *(float2*)&Sf[r * TS + c0] = make_float2(v0, v1);
            *(__half2*)&Sh[r * SH + c0] = __floats2half2_rn(v0, v1);
        }
    }
}

// fp32-only transposed-state update (half conversion deferred to derive).
template<int NI>
__device__ __forceinline__ void updateTF(float* __restrict__ Tf,
    const float* __restrict__ rs,
    float (&acc)[NI][4], int g, int tg, int mb, int nb)
{
#pragma unroll
    for (int ni = 0; ni < NI; ni++) {
        const int c0 = nb + ni * 8 + 2 * tg;
#pragma unroll
        for (int hh = 0; hh < 2; hh++) {
            const int r = mb + g + 8 * hh;
            float v0 = rs[c0]     * (Tf[r * TS + c0]     + acc[ni][2 * hh]);
            float v1 = rs[c0 + 1] * (Tf[r * TS + c0 + 1] + acc[ni][2 * hh + 1]);
            *(float2*)&Tf[r * TS + c0] = make_float2(v0, v1);
        }
    }
}

// cp.async prefetch: q,k fp16 tiles + aK,aC fp32 tiles = 3072 chunks.
__device__ __forceinline__ void scan_prefetch(
    const __half* __restrict__ q, const __half* __restrict__ k,
    const float* __restrict__ aK, const float* __restrict__ aC,
    uint32_t smbase, int tid, size_t off)
{
#pragma unroll
    for (int i = 0; i < 6; i++) {
        const int id = tid + i * 512;
        uint32_t dst;
        const void* src;
        if (id < 1024) {
            const int t8 = id >> 9, loc = id & 511;
            const int r = loc >> 3, c8 = (loc & 7) * 8;
            const __half* s = (t8 == 0) ? q : k;
            src = s + off + (size_t)loc * 8;
            dst = smbase + (uint32_t)(t8 * 9216 + (r * SH + c8) * 2);
        } else {
            const int t4 = (id - 1024) >> 10, loc = (id - 1024) & 1023;
            const int r = loc >> 4, c4 = (loc & 15) * 4;
            const float* s = (t4 == 0) ? aK : aC;
            src = s + off + (size_t)loc * 4;
            dst = smbase + (uint32_t)(O_AKF + t4 * 18432 + (r * TS + c4) * 4);
        }
        asm volatile("cp.async.cg.shared.global [%0], [%1], 16;" :: "r"(dst), "l"(src));
    }
    asm volatile("cp.async.commit_group;");
}

__global__ __launch_bounds__(512) void scan_chunked(
    const __half* __restrict__ qp, const __half* __restrict__ kp,
    const __half* __restrict__ vp, const float* __restrict__ aKp,
    const float* __restrict__ aCp, __half* __restrict__ o2dh)
{
    extern __shared__ char smc[];
    __half* QS  = (__half*)(smc + O_QS);
    __half* KS  = (__half*)(smc + O_KS);
    float*  AKf = (float*)(smc + O_AKF);
    float*  ACf = (float*)(smc + O_ACF);
    float*  Sf  = (float*)(smc + O_SF);
    float*  CTf = (float*)(smc + O_CTF);
    float*  GTf = (float*)(smc + O_GTF);
    __half* Qh  = (__half*)(smc + O_QH);
    __half* Kh  = (__half*)(smc + O_KH);
    __half* Qt  = (__half*)(smc + O_QT);
    __half* QtT = (__half*)(smc + O_QTT);
    __half* Kt  = (__half*)(smc + O_KT);
    __half* KtT = (__half*)(smc + O_KTT);
    __half* Ph  = (__half*)(smc + O_PH);
    __half* RSc = (__half*)(smc + O_RS);
    __half* Uh  = (__half*)(smc + O_UH);
    __half* Sh  = (__half*)(smc + O_SHH);
    __half* VT  = (__half*)(smc + O_VT);
    __half* KCT = (__half*)(smc + O_KCT);
    __half* CTh = (__half*)(smc + O_CTH);
    __half* GTh = (__half*)(smc + O_GTH);
    __shared__ float aKL[64], aCL[64];

    const int bh   = blockIdx.x >> 1;
    const int half = blockIdx.x & 1;
    const int b = bh >> 4, h = bh & 15;
    const size_t base = (size_t)bh * TSZ * DH;
    const int tid  = threadIdx.x;
    const int lane = tid & 31, w = tid >> 5;
    const int wg = w >> 3, w8 = w & 7;
    const int g = lane >> 2, tg = lane & 3;
    const int mb4 = (w8 & 3) * 16, nb4 = (w8 >> 2) * 32;
    const int mb2 = (w8 & 3) * 16, nb2 = (w8 >> 2) * 16;
    const int mbF = (w8 & 1) * 16, nbF = (w8 >> 1) * 16;
    const uint32_t smbase = (uint32_t)__cvta_generic_to_shared(smc);

    for (int i = tid; i < 9216; i += 512) ((uint32_t*)(smc + O_SF))[i] = 0;
    for (int i = tid; i < 2304; i += 512) ((uint32_t*)(smc + O_SHH))[i] = 0;
    for (int i = tid; i < 2304; i += 512) ((uint32_t*)(smc + O_CTH))[i] = 0;

    scan_prefetch(qp, kp, aKp, aCp, smbase, tid, base);
    __syncthreads();

    for (int ch = 0; ch < NCHUNK; ch++) {
        const size_t off = base + (size_t)ch * CL * DH;
        {   // V (fp16 source) half-column -> VT transposed
            const int r = tid >> 3, c4 = (tid & 7) * 4;
            __half2 hv[2];
            *(uint2*)hv = *(const uint2*)(vp + off + r * DH + half * 32 + c4);
            VT[(c4 + 0) * SH + r] = __low2half(hv[0]);
            VT[(c4 + 1) * SH + r] = __high2half(hv[0]);
            VT[(c4 + 2) * SH + r] = __low2half(hv[1]);
            VT[(c4 + 3) * SH + r] = __high2half(hv[1]);
        }
        asm volatile("cp.async.wait_group 0;");
        __syncthreads();

        {   // cumulative products: 2 tensors x 4 segments of 16 rows
            float* Tt = (tid < 256) ? AKf : ACf;
            const int col = tid & 63;
            const int seg = (tid >> 6) & 3;
            const int r0 = seg * 16;
            float p = 1.f;
#pragma unroll
            for (int r = 0; r < 16; r++) {
                p *= Tt[(r0 + r) * TS + col];
                Tt[(r0 + r) * TS + col] = p;
            }
            __syncthreads();
            float pref = 1.f;
#pragma unroll
            for (int s = 0; s < 3; s++)
                if (s < seg) pref *= Tt[(s * 16 + 15) * TS + col];
            __syncthreads();
            if (seg > 0) {
#pragma unroll
                for (int r = 0; r < 16; r++) Tt[(r0 + r) * TS + col] *= pref;
            }
        }
        __syncthreads();

        // derive fp16 operand tiles (+ SCL fp32) + deferred state conversion
#pragma unroll
        for (int i = 0; i < 8; i++) {
            const int e = tid + i * 512;
            const int r = e >> 6, c = e & 63;
            const int idx = r * TS + c;
            const float ak = AKf[idx], ac = ACf[idx];
            const float qv = __half2float(QS[r * SH + c]);
            const float kv = __half2float(KS[r * SH + c]);
            if (r == 63) { aKL[c] = ak; aCL[c] = ac; }
            const float qh = qv * ak, kt = kv / ak;
            const float qt = qv / ac, kh = kv * ac;
            Qh[r * SH + c]  = __float2half_rn(qh);
            Kh[r * SH + c]  = __float2half_rn(kh);
            Qt[r * SH + c]  = __float2half_rn(qt);
            QtT[c * SH + r] = __float2half_rn(qt);
            Kt[r * SH + c]  = __float2half_rn(kt);
            KtT[c * SH + r] = __float2half_rn(kt);
            AKf[idx] = ak * ac;          // SCL
        }
        // convert fp32 C/G states (from previous chunk's F) to fp16
#pragma unroll
        for (int i = 0; i < 4; i++) {
            const int e = tid + i * 512;          // 0..2047 = 32x64
            const int r = e >> 6, c = e & 63;
            CTh[r * SH + c] = __float2half_rn(CTf[r * TS + c]);
            GTh[r * SH + c] = __float2half_rn(GTf[r * TS + c]);
        }
        __syncthreads();

        float acc4[4][4];
        float acc2[2][4];

        // Phase A
        if (wg == 0) {
            zacc(acc4);
            mmh<4, false>(Kh, Qt, acc4, lane, mb4, nb4);
            storeH<4, 2, false>(RSc, nullptr, acc4, g, tg, mb4, nb4);
        } else {
            zacc(acc4);
            mmh<4, false>(Qh, Kt, acc4, lane, mb4, nb4);
            storeH<4, 1, false>(Ph, nullptr, acc4, g, tg, mb4, nb4);
        }
        __syncthreads();

        // Phase B
        if (wg == 0) {
            zacc(acc2);
            mmh<2, false>(Kh,  CTh, acc2, lane, mb2, nb2);
            mmh<2, false>(RSc, VT,  acc2, lane, mb2, nb2);
            storeHT<2>(KCT, acc2, g, tg, mb2, nb2);
        } else {
            zacc(acc4);
            mmh<4, false>(Qh, Sh,  acc4, lane, mb4, nb4);
            mmh<4, false>(Ph, KtT, acc4, lane, mb4, nb4);
            storeH<4, 0, true>(Uh, AKf, acc4, g, tg, mb4, nb4);
        }
        __syncthreads();

        // staging dead: prefetch next chunk
        {
            int chn = ch + 1; if (chn > NCHUNK - 1) chn = NCHUNK - 1;
            scan_prefetch(qp, kp, aKp, aCp, smbase, tid,
                          base + (size_t)chn * CL * DH);
        }

        // Phase C
        if (wg == 0) {
            zacc(acc4);
            mmh<4, false>(Uh, Qt, acc4, lane, mb4, nb4);
            storeH<4, 1, false>(RSc, nullptr, acc4, g, tg, mb4, nb4);
        } else {
            zacc(acc4);
            mmh<4, false>(KtT, KtT, acc4, lane, mb4, nb4);
            updateS<4>(Sf, Sh, aKL, acc4, g, tg, mb4, nb4);
        }
        __syncthreads();

        // Phase E (wg0: output) || Phase F (wg1: fp32 C/G state updates)
        if (wg == 0) {
            zacc(acc2);
            mmh<2, false>(Uh,  CTh, acc2, lane, mb2, nb2);
            mmh<2, false>(RSc, VT,  acc2, lane, mb2, nb2);
            mmh<2, true >(Qh,  GTh, acc2, lane, mb2, nb2);
            mmh<2, true >(Ph,  KCT, acc2, lane, mb2, nb2);
            const int t0 = ch * CL;
#pragma unroll
            for (int ni = 0; ni < 2; ni++) {
                const int c0 = nb2 + ni * 8 + 2 * tg;
#pragma unroll
                for (int hh = 0; hh < 2; hh++) {
                    const int r = mb2 + g + 8 * hh;
                    __half2 st = __floats2half2_rn(acc2[ni][2 * hh],
                                                   acc2[ni][2 * hh + 1]);
                    *(__half2*)&o2dh[(size_t)(b * TSZ + t0 + r) * 1024 +
                                     h * DH + half * 32 + c0] = st;
                }
            }
        } else {
            zacc(acc2);
            mmh<2, false>(VT, QtT, acc2, lane, mbF, nbF);
            updateTF<2>(CTf, aCL, acc2, g, tg, mbF, nbF);
            zacc(acc2);
            mmh<2, false>(KCT, KtT, acc2, lane, mbF, nbF);
            updateTF<2>(GTf, aKL, acc2, g, tg, mbF, nbF);
        }
        __syncthreads();
    }
}

// ---------------------------------------------------------------------------
extern "C" void kernel_launch(void* const* d_in, const int* in_sizes, int n_in,
                              void* d_out, int out_size)
{
    const float* x   = (const float*)d_in[0];
    const float* Wq  = (const float*)d_in[1];
    const float* Wk  = (const float*)d_in[2];
    const float* Wv  = (const float*)d_in[3];
    const float* WgK = (const float*)d_in[4];
    const float* bgK = (const float*)d_in[5];
    const float* WgC = (const float*)d_in[6];
    const float* bgC = (const float*)d_in[7];
    const float* Wo  = (const float*)d_in[8];
    float* out = (float*)d_out;

    __half *projh = nullptr, *o2dh = nullptr, *xh = nullptr, *wth = nullptr;
    float  *projf = nullptr;
    cudaGetSymbolAddress((void**)&projh, g_projh);
    cudaGetSymbolAddress((void**)&projf, g_projf);
    cudaGetSymbolAddress((void**)&o2dh,  g_o2dh);
    cudaGetSymbolAddress((void**)&xh,    g_xh);
    cudaGetSymbolAddress((void**)&wth,   g_wth);
    const size_t PS = (size_t)64 * TSZ * DH;

    cudaFuncSetAttribute(gemm_fp16,
                         cudaFuncAttributeMaxDynamicSharedMemorySize,
                         GEMM2_SMEM);
    cudaFuncSetAttribute(scan_chunked,
                         cudaFuncAttributeMaxDynamicSharedMemorySize,
                         SCAN_SMEM_BYTES);

    half_x_kernel<<<(GM * GK) / 2048, 256>>>(x, xh);
    half_wt_kernel<<<dim3(32, 32, 6), 256>>>(Wq, Wk, Wv, WgK, WgC, Wo, wth);

    gemm_fp16<<<dim3(GN / 256, GM / 128, 5), 512, GEMM2_SMEM>>>(
        xh, wth, bgK, bgC, projf, projh, 1);

    scan_chunked<<<128, 512, SCAN_SMEM_BYTES>>>(
        projh, projh + PS, projh + 2 * PS, projf, projf + PS, o2dh);

    gemm_fp16<<<dim3(GN / 256, GM / 128, 1), 512, GEMM2_SMEM>>>(
        o2dh, wth + (size_t)5 * GN * GK, nullptr, nullptr, out, nullptr, 0);
}